// round 3
// baseline (speedup 1.0000x reference)
#include <cuda_runtime.h>
#include <math.h>

#define BINSIZE      200
#define BINWIDTH     500
#define N_CLUSTERS   20
#define N_ROI_MAX    200
#define N_CELLS_MAX  100352   // 100000 rounded up to 16B multiple for vec copy

// Precomputed log-density table: [n_roi, n_clusters, BINWIDTH]
__device__ float g_heights[N_ROI_MAX * N_CLUSTERS * BINWIDTH];
// labels compacted to uint8
__device__ unsigned char g_labels8[N_CELLS_MAX];

// ---------------------------------------------------------------------------
// Kernel 1 (fused): heights build (warp per row) + label int32->uint8 pack.
// ---------------------------------------------------------------------------
__global__ void __launch_bounds__(256) build_kernel(
    const float* __restrict__ baseline,
    const float* __restrict__ delta,
    const int*   __restrict__ regions_oi,
    const int*   __restrict__ labels,
    int n_rows, int n_clusters, int rowBlocks, int n_cells)
{
    if ((int)blockIdx.x < rowBlocks) {
        const int warp = (int)blockIdx.x * 8 + ((int)threadIdx.x >> 5);
        if (warp >= n_rows) return;
        const int lane = threadIdx.x & 31;
        const int roi = warp / n_clusters;
        const int cl  = warp - roi * n_clusters;
        const int region = regions_oi[roi];

        const float4* __restrict__ b4 = (const float4*)(baseline + (long long)region * BINWIDTH);
        const float4* __restrict__ d4 = (const float4*)(delta + ((long long)region * n_clusters + cl) * BINWIDTH);

        float4 v[4];
        float m = -INFINITY;
        #pragma unroll
        for (int it = 0; it < 4; it++) {
            const int idx = lane + it * 32;
            if (idx < 125) {
                float4 a = b4[idx];
                float4 d = d4[idx];
                v[it].x = a.x + d.x; v[it].y = a.y + d.y;
                v[it].z = a.z + d.z; v[it].w = a.w + d.w;
                m = fmaxf(m, fmaxf(fmaxf(v[it].x, v[it].y), fmaxf(v[it].z, v[it].w)));
            }
        }
        #pragma unroll
        for (int o = 16; o > 0; o >>= 1)
            m = fmaxf(m, __shfl_xor_sync(0xffffffffu, m, o));

        float s = 0.0f;
        #pragma unroll
        for (int it = 0; it < 4; it++) {
            const int idx = lane + it * 32;
            if (idx < 125) {
                s += __expf(v[it].x - m) + __expf(v[it].y - m)
                   + __expf(v[it].z - m) + __expf(v[it].w - m);
            }
        }
        #pragma unroll
        for (int o = 16; o > 0; o >>= 1)
            s += __shfl_xor_sync(0xffffffffu, s, o);

        const float sub = m + __logf(s) + logf((float)BINSIZE);

        float4* __restrict__ o4 = (float4*)(g_heights + (long long)warp * BINWIDTH);
        #pragma unroll
        for (int it = 0; it < 4; it++) {
            const int idx = lane + it * 32;
            if (idx < 125) {
                float4 h;
                h.x = v[it].x - sub; h.y = v[it].y - sub;
                h.z = v[it].z - sub; h.w = v[it].w - sub;
                o4[idx] = h;
            }
        }
    } else {
        const int b = (int)blockIdx.x - rowBlocks;
        const int t = b * 256 + (int)threadIdx.x;
        const int i0 = t * 4;
        if (i0 + 4 <= n_cells) {
            const int4 l = ((const int4*)labels)[t];
            uchar4 p;
            p.x = (unsigned char)l.x; p.y = (unsigned char)l.y;
            p.z = (unsigned char)l.z; p.w = (unsigned char)l.w;
            ((uchar4*)g_labels8)[t] = p;
        } else {
            for (int i = i0; i < n_cells; i++)
                g_labels8[i] = (unsigned char)labels[i];
        }
    }
}

// ---------------------------------------------------------------------------
// Kernel 2: persistent gather. Labels table lives in shared memory (LDS
// gathers instead of 32-wavefront L1tex gathers). Grid-stride over groups
// of 8 fragments.
// ---------------------------------------------------------------------------
__global__ void __launch_bounds__(512) gather_smem_kernel(
    const int*   __restrict__ coords,      // [n, 2]
    const int*   __restrict__ lrix,        // [n]
    const int*   __restrict__ lcix,        // [n]
    const float* __restrict__ inside,      // [1]
    float*       __restrict__ out,         // [n, 2]
    int n, int n_cells, int n_groups)
{
    extern __shared__ unsigned char s_labels[];

    // Cooperative fill of the label table (16B chunks; g_labels8 padded).
    {
        const int nvec = (n_cells + 15) >> 4;
        const int4* src = (const int4*)g_labels8;
        int4* dst = (int4*)s_labels;
        for (int i = threadIdx.x; i < nvec; i += blockDim.x)
            dst[i] = src[i];
    }
    __syncthreads();

    const float x    = inside[0];
    const float l1p  = log1pf(expf(-x));
    const float lpIn  = -l1p     - logf((float)BINWIDTH);
    const float lpOut = -x - l1p - logf((float)(100000 - BINWIDTH));

    const int gtid    = blockIdx.x * blockDim.x + threadIdx.x;
    const int gstride = gridDim.x * blockDim.x;

    for (int g = gtid; g < n_groups; g += gstride) {
        const int i0 = g * 8;
        if (i0 + 8 <= n) {
            int4 c[4], rr[2], qq[2];
            #pragma unroll
            for (int k = 0; k < 4; k++) c[k] = ((const int4*)coords)[g * 4 + k];
            #pragma unroll
            for (int k = 0; k < 2; k++) rr[k] = ((const int4*)lrix)[g * 2 + k];
            #pragma unroll
            for (int k = 0; k < 2; k++) qq[k] = ((const int4*)lcix)[g * 2 + k];

            // label gathers from shared memory
            int lab[8];
            lab[0] = s_labels[qq[0].x]; lab[1] = s_labels[qq[0].y];
            lab[2] = s_labels[qq[0].z]; lab[3] = s_labels[qq[0].w];
            lab[4] = s_labels[qq[1].x]; lab[5] = s_labels[qq[1].y];
            lab[6] = s_labels[qq[1].z]; lab[7] = s_labels[qq[1].w];

            int bl[8], br[8], r[8];
            #pragma unroll
            for (int k = 0; k < 4; k++) {
                bl[2*k]   = c[k].x / BINSIZE; br[2*k]   = c[k].y / BINSIZE;
                bl[2*k+1] = c[k].z / BINSIZE; br[2*k+1] = c[k].w / BINSIZE;
            }
            r[0] = rr[0].x; r[1] = rr[0].y; r[2] = rr[0].z; r[3] = rr[0].w;
            r[4] = rr[1].x; r[5] = rr[1].y; r[6] = rr[1].z; r[7] = rr[1].w;

            float L[8];
            #pragma unroll
            for (int k = 0; k < 8; k++)
                L[k] = g_heights[(r[k] * N_CLUSTERS + lab[k]) * BINWIDTH + bl[k]];

            #pragma unroll
            for (int k = 0; k < 4; k++) {
                float4 o;
                o.x = L[2*k];   o.y = (bl[2*k]   == br[2*k])   ? lpIn : lpOut;
                o.z = L[2*k+1]; o.w = (bl[2*k+1] == br[2*k+1]) ? lpIn : lpOut;
                ((float4*)out)[g * 4 + k] = o;
            }
        } else {
            for (int i = i0; i < n; i++) {
                const int cx = coords[i * 2 + 0];
                const int cy = coords[i * 2 + 1];
                const int bl = cx / BINSIZE, br = cy / BINSIZE;
                const int lab = s_labels[lcix[i]];
                const int rg = lrix[i];
                out[i * 2 + 0] = g_heights[(rg * N_CLUSTERS + lab) * BINWIDTH + bl];
                out[i * 2 + 1] = (bl == br) ? lpIn : lpOut;
            }
        }
    }
}

// Fallback (labels table too big for smem): previous global-gather version.
__global__ void __launch_bounds__(256) gather_global_kernel(
    const int*   __restrict__ coords,
    const int*   __restrict__ lrix,
    const int*   __restrict__ lcix,
    const float* __restrict__ inside,
    float*       __restrict__ out,
    int n)
{
    const int tid = blockIdx.x * blockDim.x + threadIdx.x;
    const int i0  = tid * 8;
    if (i0 >= n) return;

    const float x    = inside[0];
    const float l1p  = log1pf(expf(-x));
    const float lpIn  = -l1p     - logf((float)BINWIDTH);
    const float lpOut = -x - l1p - logf((float)(100000 - BINWIDTH));

    for (int i = i0; i < n && i < i0 + 8; i++) {
        const int cx = coords[i * 2 + 0];
        const int cy = coords[i * 2 + 1];
        const int bl = cx / BINSIZE, br = cy / BINSIZE;
        const int lab = g_labels8[lcix[i]];
        const int rg = lrix[i];
        out[i * 2 + 0] = g_heights[(rg * N_CLUSTERS + lab) * BINWIDTH + bl];
        out[i * 2 + 1] = (bl == br) ? lpIn : lpOut;
    }
}

// ---------------------------------------------------------------------------
extern "C" void kernel_launch(void* const* d_in, const int* in_sizes, int n_in,
                              void* d_out, int out_size)
{
    const float* baseline = (const float*)d_in[0];
    const float* delta    = (const float*)d_in[1];
    const float* inside   = (const float*)d_in[2];
    const int*   regions  = (const int*)d_in[3];
    const int*   coords   = (const int*)d_in[4];
    const int*   lrix     = (const int*)d_in[5];
    const int*   lcix     = (const int*)d_in[6];
    const int*   labels   = (const int*)d_in[7];
    float*       out      = (float*)d_out;

    const int n_roi      = in_sizes[3];
    const int n          = in_sizes[5];
    const int n_cells    = in_sizes[7];
    const int n_regions  = in_sizes[0] / BINWIDTH;
    const int n_clusters = (n_regions > 0) ? (in_sizes[1] / (n_regions * BINWIDTH)) : N_CLUSTERS;

    const int n_rows    = n_roi * n_clusters;
    const int rowBlocks = (n_rows + 7) / 8;
    const int packBlocks = (n_cells + 1023) / 1024;
    build_kernel<<<rowBlocks + packBlocks, 256>>>(
        baseline, delta, regions, labels, n_rows, n_clusters, rowBlocks, n_cells);

    const int n_groups = (n + 7) / 8;
    const int smemBytes = ((n_cells + 15) & ~15);
    if (n_cells <= N_CELLS_MAX && smemBytes <= 100352) {
        static bool attr_set = false;
        if (!attr_set) {
            cudaFuncSetAttribute(gather_smem_kernel,
                                 cudaFuncAttributeMaxDynamicSharedMemorySize, 100352);
            attr_set = true;
        }
        gather_smem_kernel<<<296, 512, smemBytes>>>(
            coords, lrix, lcix, inside, out, n, n_cells, n_groups);
    } else {
        const int blocks = (n_groups + 255) / 256;
        gather_global_kernel<<<blocks, 256>>>(coords, lrix, lcix, inside, out, n);
    }
}